// round 4
// baseline (speedup 1.0000x reference)
#include <cuda_runtime.h>
#include <math.h>

#define Hn     8
#define Nn     512
#define Dn     64
#define DNn    128
#define DEn    64
#define INNERn 512

typedef unsigned long long ull;

__device__ __forceinline__ ull pk2(float lo, float hi) {
    ull r; asm("mov.b64 %0,{%1,%2};" : "=l"(r) : "f"(lo), "f"(hi)); return r;
}
__device__ __forceinline__ float2 upk2(ull v) {
    float2 r; asm("mov.b64 {%0,%1},%2;" : "=f"(r.x), "=f"(r.y) : "l"(v)); return r;
}
__device__ __forceinline__ void fma2(ull& d, ull a, ull b) {
    asm("fma.rn.f32x2 %0,%1,%2,%3;" : "=l"(d) : "l"(a), "l"(b), "l"(d));
}

// ---------------- scratch ----------------
__device__ float g_q  [Hn * Nn * Dn];
__device__ float g_k  [Hn * Nn * Dn];
__device__ float g_v  [Hn * Nn * Dn];
__device__ float g_qe [Hn * Nn * DEn];
__device__ float g_qbe[Hn * Nn];
__device__ float g_sim[Hn * Nn * Nn];    // logits, then unnormalized p
__device__ float g_sinv[Hn * Nn];
__device__ float g_att[Hn * Nn * Dn];
__device__ float g_ew [Hn * Nn * DEn];
__device__ float g_M  [INNERn * DNn];
__device__ float g_bvec[DNn];

// ---------------- kernel 1: QKV projection (+ fused qe, qbe) --------
__global__ void __launch_bounds__(256)
qkv_kernel(const float* __restrict__ nodes,
           const float* __restrict__ Wq, const float* __restrict__ bq,
           const float* __restrict__ Wk, const float* __restrict__ bk,
           const float* __restrict__ Wv, const float* __restrict__ bv,
           const float* __restrict__ We, const float* __restrict__ be)
{
    __shared__ float sN[32][DNn];
    __shared__ float sW[DNn][64];

    const int it = blockIdx.x;
    const int ct = blockIdx.y;
    const int mat = ct >> 3;
    const int h   = ct & 7;
    const int colbase = h * 64;
    const float* W    = (mat == 0) ? Wq : (mat == 1 ? Wk : Wv);
    const float* bias = (mat == 0) ? bq : (mat == 1 ? bk : bv);
    float* out        = (mat == 0) ? g_q : (mat == 1 ? g_k : g_v);

    const int i0 = it * 32;
    const int t  = threadIdx.x;

    {
        const float4* nf = (const float4*)(nodes + (size_t)i0 * DNn);
        float4* sNf = (float4*)&sN[0][0];
        #pragma unroll
        for (int r = 0; r < 4; r++) sNf[t + 256 * r] = nf[t + 256 * r];
    }
    #pragma unroll
    for (int r = 0; r < 8; r++) {
        int idx = t + 256 * r;
        int f = idx >> 4, c4 = idx & 15;
        ((float4*)&sW[f][0])[c4] = *(const float4*)(W + (size_t)f * INNERn + colbase + c4 * 4);
    }
    __syncthreads();

    const int col   = t & 63;
    const int ibase = t >> 6;
    float acc[8];
    #pragma unroll
    for (int r = 0; r < 8; r++) acc[r] = 0.f;

    for (int f = 0; f < DNn; f++) {
        float w = sW[f][col];
        #pragma unroll
        for (int r = 0; r < 8; r++) acc[r] += sN[ibase + 4 * r][f] * w;
    }

    const float b  = bias[colbase + col];
    const float sc = (mat == 0) ? 0.125f : 1.0f;
    float vals[8];
    #pragma unroll
    for (int r = 0; r < 8; r++) {
        vals[r] = (acc[r] + b) * sc;
        int i = i0 + ibase + 4 * r;
        out[(size_t)h * (Nn * Dn) + (size_t)i * Dn + col] = vals[r];
    }

    if (mat == 0) {
        float (*sOut)[Dn] = (float(*)[Dn])&sW[0][0];
        __syncthreads();
        #pragma unroll
        for (int r = 0; r < 8; r++) sOut[ibase + 4 * r][col] = vals[r];
        __syncthreads();

        float wreg[Dn];
        #pragma unroll
        for (int d = 0; d < Dn; d++) wreg[d] = We[(size_t)col * INNERn + colbase + d];
        #pragma unroll
        for (int r = 0; r < 8; r++) {
            int i = i0 + ibase + 4 * r;
            float s = 0.f;
            #pragma unroll
            for (int d = 0; d < Dn; d++) s += wreg[d] * sOut[ibase + 4 * r][d];
            g_qe[(size_t)h * (Nn * DEn) + (size_t)i * DEn + col] = s;
        }
        if (col == 0) {
            #pragma unroll
            for (int r = 0; r < 8; r++) {
                int i = i0 + ibase + 4 * r;
                float sb = 0.f;
                for (int d = 0; d < Dn; d++) sb += sOut[ibase + 4 * r][d] * be[colbase + d];
                g_qbe[h * Nn + i] = sb;
            }
        }
    }
}

// ---------------- kernel 2: combined weight precompute + bvec ----------------
__global__ void __launch_bounds__(256)
wcomb_kernel(const float* __restrict__ We, const float* __restrict__ be,
             const float* __restrict__ Wo, const float* __restrict__ bo)
{
    const int b = blockIdx.x;
    const int t = threadIdx.x;
    if (b < 64) {
        const int h  = b >> 3;
        const int c0 = (b & 7) * 8 + (t >> 7) * 4;
        const int o  = t & 127;
        float acc[4] = {0.f, 0.f, 0.f, 0.f};
        for (int d = 0; d < 64; d++) {
            float wo = Wo[(size_t)(h * 64 + d) * DNn + o];
            #pragma unroll
            for (int cc = 0; cc < 4; cc++)
                acc[cc] += We[(size_t)(c0 + cc) * INNERn + h * 64 + d] * wo;
        }
        #pragma unroll
        for (int cc = 0; cc < 4; cc++)
            g_M[(size_t)(h * 64 + c0 + cc) * DNn + o] = acc[cc];
    } else {
        if (t < 128) {
            float acc = bo[t];
            for (int k = 0; k < INNERn; k++) acc += be[k] * Wo[(size_t)k * DNn + t];
            g_bvec[t] = acc;
        }
    }
}

// ---------------- kernel 3: sim = q @ k^T + qbe ----------------
__global__ void __launch_bounds__(256)
qksim_kernel(const float* __restrict__ kmat)
{
    __shared__ float sQT[64][36];
    __shared__ float sKT[64][132];

    const int i0 = blockIdx.x * 32;
    const int j0 = blockIdx.y * 128;
    const int h  = blockIdx.z;
    const int t  = threadIdx.x;

    #pragma unroll
    for (int r = 0; r < 2; r++) {
        int idx = t + 256 * r;
        int i = idx >> 4, d4 = (idx & 15) * 4;
        float4 v = *(const float4*)(g_q + (size_t)h * (Nn * Dn) + (size_t)(i0 + i) * Dn + d4);
        sQT[d4 + 0][i] = v.x; sQT[d4 + 1][i] = v.y; sQT[d4 + 2][i] = v.z; sQT[d4 + 3][i] = v.w;
    }
    #pragma unroll
    for (int r = 0; r < 8; r++) {
        int idx = t + 256 * r;
        int j = idx >> 4, d4 = (idx & 15) * 4;
        float4 v = *(const float4*)(kmat + (size_t)h * (Nn * Dn) + (size_t)(j0 + j) * Dn + d4);
        sKT[d4 + 0][j] = v.x; sKT[d4 + 1][j] = v.y; sKT[d4 + 2][j] = v.z; sKT[d4 + 3][j] = v.w;
    }
    __syncthreads();

    const int ii0 = (t >> 5) * 4;
    const int jj0 = (t & 31) * 4;
    float acc[4][4];
    #pragma unroll
    for (int u = 0; u < 4; u++)
        #pragma unroll
        for (int v = 0; v < 4; v++) acc[u][v] = 0.f;

    #pragma unroll 4
    for (int d = 0; d < 64; d++) {
        float4 rq = *(const float4*)&sQT[d][ii0];
        float4 rk = *(const float4*)&sKT[d][jj0];
        acc[0][0] += rq.x * rk.x; acc[0][1] += rq.x * rk.y; acc[0][2] += rq.x * rk.z; acc[0][3] += rq.x * rk.w;
        acc[1][0] += rq.y * rk.x; acc[1][1] += rq.y * rk.y; acc[1][2] += rq.y * rk.z; acc[1][3] += rq.y * rk.w;
        acc[2][0] += rq.z * rk.x; acc[2][1] += rq.z * rk.y; acc[2][2] += rq.z * rk.z; acc[2][3] += rq.z * rk.w;
        acc[3][0] += rq.w * rk.x; acc[3][1] += rq.w * rk.y; acc[3][2] += rq.w * rk.z; acc[3][3] += rq.w * rk.w;
    }

    #pragma unroll
    for (int u = 0; u < 4; u++) {
        float qbe = g_qbe[h * Nn + i0 + ii0 + u];
        float4 o = make_float4(acc[u][0] + qbe, acc[u][1] + qbe, acc[u][2] + qbe, acc[u][3] + qbe);
        *(float4*)(g_sim + ((size_t)(h * Nn + i0 + ii0 + u)) * Nn + j0 + jj0) = o;
    }
}

// ---------------- kernel 4: fused per-node edge pipeline ----------------
// grid 512 (one per node i), 256 threads, ~190KB dynamic smem.
// sim += qe.edges ; softmax ; p -> g_sim ; ew = (p@edges)*sinv -> g_ew
#define OFF_SIM  0                      // 8*512 floats
#define OFF_QE   4096                   // 8*64
#define OFF_SINV 4608                   // 16
#define OFF_RED  4624                   // 8w*8h*32cp ull = 8192 floats
#define OFF_E    12816                  // 512 rows * 68 floats
#define EROW     68
#define EA_SMEM  ((OFF_E + Nn * EROW) * 4)

__global__ void __launch_bounds__(256, 1)
edge_attn_kernel(const float* __restrict__ edges)
{
    extern __shared__ float sm[];
    float* sSim  = sm + OFF_SIM;
    float* sQE   = sm + OFF_QE;
    float* sSinv = sm + OFF_SINV;
    ull*   sRed  = (ull*)(sm + OFF_RED);
    float* sE    = sm + OFF_E;

    const int i = blockIdx.x;
    const int t = threadIdx.x;
    const int w = t >> 5, l = t & 31;

    // load sim rows (8 x 512) and qe (8 x 64)
    #pragma unroll
    for (int r = 0; r < 4; r++) {
        int idx = t + 256 * r;
        int h = idx >> 7, j4 = (idx & 127) * 4;
        *(float4*)&sSim[h * 512 + j4] = *(const float4*)(g_sim + ((size_t)(h * Nn + i)) * Nn + j4);
    }
    if (t < 128) {
        int h = t >> 4, c4 = (t & 15) * 4;
        *(float4*)&sQE[h * 64 + c4] = *(const float4*)(g_qe + (size_t)h * (Nn * DEn) + (size_t)i * DEn + c4);
    }
    __syncthreads();

    // ---- stage 1: load edges[i] chunkwise + add edge-sim term
    const int jq   = t >> 2;        // 0..63 (j within chunk)
    const int quar = t & 3;         // quarter of the 64-dim c
    for (int jc = 0; jc < 8; jc++) {
        const int j0 = jc * 64;
        #pragma unroll
        for (int r = 0; r < 4; r++) {
            int idx = t + 256 * r;
            int jj = idx >> 4, c4 = (idx & 15) * 4;
            *(float4*)&sE[(j0 + jj) * EROW + c4] = *(const float4*)(edges + ((size_t)i * Nn + j0 + jj) * DEn + c4);
        }
        __syncthreads();

        ulonglong2 er[4];
        const ulonglong2* ep = (const ulonglong2*)&sE[(j0 + jq) * EROW + quar * 16];
        #pragma unroll
        for (int q = 0; q < 4; q++) er[q] = ep[q];

        #pragma unroll
        for (int h = 0; h < Hn; h++) {
            const ulonglong2* qp = (const ulonglong2*)&sQE[h * 64 + quar * 16];
            ull a0 = 0, a1 = 0;
            #pragma unroll
            for (int q = 0; q < 4; q++) {
                ulonglong2 qv = qp[q];
                fma2(a0, qv.x, er[q].x);
                fma2(a1, qv.y, er[q].y);
            }
            float2 f0 = upk2(a0), f1 = upk2(a1);
            float s = f0.x + f0.y + f1.x + f1.y;
            s += __shfl_xor_sync(0xffffffffu, s, 1);
            s += __shfl_xor_sync(0xffffffffu, s, 2);
            if (quar == 0) sSim[h * 512 + j0 + jq] += s;
        }
        __syncthreads();
    }

    // ---- stage 2: softmax (warp w = head w), p kept unnormalized in sSim
    {
        float vals[16];
        float mx = -1e30f;
        #pragma unroll
        for (int jc = 0; jc < 16; jc++) {
            vals[jc] = sSim[w * 512 + jc * 32 + l];
            mx = fmaxf(mx, vals[jc]);
        }
        #pragma unroll
        for (int off = 16; off > 0; off >>= 1) mx = fmaxf(mx, __shfl_xor_sync(0xffffffffu, mx, off));
        float s = 0.f;
        #pragma unroll
        for (int jc = 0; jc < 16; jc++) {
            float e = __expf(vals[jc] - mx);
            s += e;
            sSim[w * 512 + jc * 32 + l] = e;
        }
        #pragma unroll
        for (int off = 16; off > 0; off >>= 1) s += __shfl_xor_sync(0xffffffffu, s, off);
        if (l == 0) sSinv[w] = 1.0f / s;
    }
    __syncthreads();

    // ---- stage 3: write p back for pv kernel
    #pragma unroll
    for (int r = 0; r < 4; r++) {
        int idx = t + 256 * r;
        int h = idx >> 7, j4 = (idx & 127) * 4;
        *(float4*)(g_sim + ((size_t)(h * Nn + i)) * Nn + j4) = *(const float4*)&sSim[h * 512 + j4];
    }
    if (t < 8) g_sinv[t * Nn + i] = sSinv[t];

    // ---- stage 4: ew accumulation. warp w owns j in [w*64, w*64+64), lane owns c-pair.
    {
        ull acc[Hn];
        #pragma unroll
        for (int h = 0; h < Hn; h++) acc[h] = 0ull;
        const int jbase = w * 64;
        for (int j = 0; j < 64; j++) {
            ull e2 = *(const ull*)&sE[(jbase + j) * EROW + 2 * l];
            #pragma unroll
            for (int h = 0; h < Hn; h++) {
                float p = sSim[h * 512 + jbase + j];   // uniform -> LDS broadcast
                fma2(acc[h], pk2(p, p), e2);
            }
        }
        #pragma unroll
        for (int h = 0; h < Hn; h++) sRed[w * 256 + h * 32 + l] = acc[h];
    }
    __syncthreads();

    // ---- stage 5: cross-warp reduce + write ew
    {
        const int h  = t >> 5;
        const int cp = t & 31;
        float ax = 0.f, ay = 0.f;
        #pragma unroll
        for (int ww = 0; ww < 8; ww++) {
            float2 f = upk2(sRed[ww * 256 + h * 32 + cp]);
            ax += f.x; ay += f.y;
        }
        float s = sSinv[h];
        *(float2*)(g_ew + (size_t)h * (Nn * DEn) + (size_t)i * DEn + 2 * cp) = make_float2(ax * s, ay * s);
    }
}

// ---------------- kernel 5: att = (p @ v) * sinv ----------------
__global__ void __launch_bounds__(256)
pv_kernel(const float* __restrict__ vmat)
{
    __shared__ float sPT[64][36];
    __shared__ float sV [64][68];

    const int i0 = blockIdx.x * 32;
    const int h  = blockIdx.y;
    const int t  = threadIdx.x;
    const int i0t = (t >> 4) * 2;
    const int d0  = (t & 15) * 4;

    float acc[2][4];
    #pragma unroll
    for (int u = 0; u < 2; u++)
        #pragma unroll
        for (int v = 0; v < 4; v++) acc[u][v] = 0.f;

    for (int jc = 0; jc < 8; jc++) {
        const int j0 = jc * 64;
        #pragma unroll
        for (int r = 0; r < 2; r++) {
            int idx = t + 256 * r;
            int ii = idx >> 4, jj4 = (idx & 15) * 4;
            float4 v = *(const float4*)(g_sim + ((size_t)(h * Nn + i0 + ii)) * Nn + j0 + jj4);
            sPT[jj4 + 0][ii] = v.x; sPT[jj4 + 1][ii] = v.y; sPT[jj4 + 2][ii] = v.z; sPT[jj4 + 3][ii] = v.w;
        }
        #pragma unroll
        for (int r = 0; r < 4; r++) {
            int idx = t + 256 * r;
            int jj = idx >> 4, d4 = (idx & 15) * 4;
            *(float4*)&sV[jj][d4] = *(const float4*)(vmat + (size_t)h * (Nn * Dn) + (size_t)(j0 + jj) * Dn + d4);
        }
        __syncthreads();

        #pragma unroll 4
        for (int jj = 0; jj < 64; jj++) {
            float2 rp = *(const float2*)&sPT[jj][i0t];
            float4 rv = *(const float4*)&sV[jj][d0];
            acc[0][0] += rp.x * rv.x; acc[0][1] += rp.x * rv.y; acc[0][2] += rp.x * rv.z; acc[0][3] += rp.x * rv.w;
            acc[1][0] += rp.y * rv.x; acc[1][1] += rp.y * rv.y; acc[1][2] += rp.y * rv.z; acc[1][3] += rp.y * rv.w;
        }
        __syncthreads();
    }

    #pragma unroll
    for (int u = 0; u < 2; u++) {
        float s = g_sinv[h * Nn + i0 + i0t + u];
        float4 o = make_float4(acc[u][0] * s, acc[u][1] * s, acc[u][2] * s, acc[u][3] * s);
        *(float4*)(g_att + (size_t)h * (Nn * Dn) + (size_t)(i0 + i0t + u) * Dn + d0) = o;
    }
}

// ---------------- kernel 6: out = [att|ew] @ [Wo;M] + bvec ----------------
__global__ void __launch_bounds__(256)
fuse_out_kernel(const float* __restrict__ Wo, float* __restrict__ out)
{
    __shared__ float sA[8][1024];
    const int t = threadIdx.x;
    const int i0 = blockIdx.x * 8;
    const int colbase = blockIdx.y * 64;

    #pragma unroll
    for (int u = 0; u < 8; u++) {
        int idx = t + 256 * u;
        int r = idx >> 8, seg = idx & 255;
        float4 val;
        if (seg < 128) {
            int h = seg >> 4, d4 = (seg & 15) * 4;
            val = *(const float4*)(g_att + (size_t)h * (Nn * Dn) + (size_t)(i0 + r) * Dn + d4);
        } else {
            int s2 = seg - 128;
            int h = s2 >> 4, c4 = (s2 & 15) * 4;
            val = *(const float4*)(g_ew + (size_t)h * (Nn * DEn) + (size_t)(i0 + r) * DEn + c4);
        }
        *(float4*)(&sA[r][ (seg & 127) * 4 + (seg < 128 ? 0 : 512) ]) = val;
    }
    __syncthreads();

    const int col = (t & 63) + colbase;
    const int rh  = t >> 6;
    const int r0  = rh * 2;
    float acc0 = 0.f, acc1 = 0.f;

    #pragma unroll 8
    for (int k = 0; k < 512; k++) {
        float w = Wo[(size_t)k * DNn + col];
        acc0 += sA[r0][k] * w;
        acc1 += sA[r0 + 1][k] * w;
    }
    #pragma unroll 8
    for (int k = 0; k < 512; k++) {
        float w = g_M[(size_t)k * DNn + col];
        acc0 += sA[r0][512 + k] * w;
        acc1 += sA[r0 + 1][512 + k] * w;
    }

    float b = g_bvec[col];
    out[(size_t)(i0 + r0) * DNn + col]     = acc0 + b;
    out[(size_t)(i0 + r0 + 1) * DNn + col] = acc1 + b;
}

// ---------------- launch ----------------
extern "C" void kernel_launch(void* const* d_in, const int* in_sizes, int n_in,
                              void* d_out, int out_size)
{
    const float* nodes = (const float*)d_in[0];
    const float* edges = (const float*)d_in[1];
    const float* Wq = (const float*)d_in[3];
    const float* bq = (const float*)d_in[4];
    const float* Wk = (const float*)d_in[5];
    const float* bk = (const float*)d_in[6];
    const float* Wv = (const float*)d_in[7];
    const float* bv = (const float*)d_in[8];
    const float* We = (const float*)d_in[9];
    const float* be = (const float*)d_in[10];
    const float* Wo = (const float*)d_in[11];
    const float* bo = (const float*)d_in[12];
    float* out = (float*)d_out;

    float* kptr; float* vptr;
    cudaGetSymbolAddress((void**)&kptr, g_k);
    cudaGetSymbolAddress((void**)&vptr, g_v);

    cudaFuncSetAttribute(edge_attn_kernel, cudaFuncAttributeMaxDynamicSharedMemorySize, EA_SMEM);

    dim3 g1(16, 24);
    qkv_kernel<<<g1, 256>>>(nodes, Wq, bq, Wk, bk, Wv, bv, We, be);
    qksim_kernel<<<dim3(16, 4, 8), 256>>>(kptr);
    wcomb_kernel<<<65, 256>>>(We, be, Wo, bo);
    edge_attn_kernel<<<Nn, 256, EA_SMEM>>>(edges);
    pv_kernel<<<dim3(16, 8), 256>>>(vptr);
    fuse_out_kernel<<<dim3(64, 2), 256>>>(Wo, out);
}

// round 5
// speedup vs baseline: 1.2526x; 1.2526x over previous
#include <cuda_runtime.h>
#include <math.h>

#define Hn     8
#define Nn     512
#define Dn     64
#define DNn    128
#define DEn    64
#define INNERn 512

typedef unsigned long long ull;

__device__ __forceinline__ ull pk2(float lo, float hi) {
    ull r; asm("mov.b64 %0,{%1,%2};" : "=l"(r) : "f"(lo), "f"(hi)); return r;
}
__device__ __forceinline__ float2 upk2(ull v) {
    float2 r; asm("mov.b64 {%0,%1},%2;" : "=f"(r.x), "=f"(r.y) : "l"(v)); return r;
}
__device__ __forceinline__ void fma2(ull& d, ull a, ull b) {
    asm("fma.rn.f32x2 %0,%1,%2,%3;" : "=l"(d) : "l"(a), "l"(b), "l"(d));
}

// ---------------- scratch ----------------
__device__ float g_q  [Hn * Nn * Dn];
__device__ float g_k  [Hn * Nn * Dn];
__device__ float g_v  [Hn * Nn * Dn];
__device__ float g_qe [Hn * Nn * DEn];
__device__ float g_qbe[Hn * Nn];
__device__ float g_sim[Hn * Nn * Nn];    // logits, then unnormalized p
__device__ float g_sinv[Hn * Nn];
__device__ float g_att[Hn * Nn * Dn];
__device__ float g_ew [Hn * Nn * DEn];
__device__ float g_M  [INNERn * DNn];
__device__ float g_bvec[DNn];

// ---------------- kernel 1: QKV projection (+ fused qe, qbe) --------
__global__ void __launch_bounds__(256)
qkv_kernel(const float* __restrict__ nodes,
           const float* __restrict__ Wq, const float* __restrict__ bq,
           const float* __restrict__ Wk, const float* __restrict__ bk,
           const float* __restrict__ Wv, const float* __restrict__ bv,
           const float* __restrict__ We, const float* __restrict__ be)
{
    __shared__ float sN[32][DNn];
    __shared__ float sW[DNn][64];

    const int it = blockIdx.x;
    const int ct = blockIdx.y;
    const int mat = ct >> 3;
    const int h   = ct & 7;
    const int colbase = h * 64;
    const float* W    = (mat == 0) ? Wq : (mat == 1 ? Wk : Wv);
    const float* bias = (mat == 0) ? bq : (mat == 1 ? bk : bv);
    float* out        = (mat == 0) ? g_q : (mat == 1 ? g_k : g_v);

    const int i0 = it * 32;
    const int t  = threadIdx.x;

    {
        const float4* nf = (const float4*)(nodes + (size_t)i0 * DNn);
        float4* sNf = (float4*)&sN[0][0];
        #pragma unroll
        for (int r = 0; r < 4; r++) sNf[t + 256 * r] = nf[t + 256 * r];
    }
    #pragma unroll
    for (int r = 0; r < 8; r++) {
        int idx = t + 256 * r;
        int f = idx >> 4, c4 = idx & 15;
        ((float4*)&sW[f][0])[c4] = *(const float4*)(W + (size_t)f * INNERn + colbase + c4 * 4);
    }
    __syncthreads();

    const int col   = t & 63;
    const int ibase = t >> 6;
    float acc[8];
    #pragma unroll
    for (int r = 0; r < 8; r++) acc[r] = 0.f;

    for (int f = 0; f < DNn; f++) {
        float w = sW[f][col];
        #pragma unroll
        for (int r = 0; r < 8; r++) acc[r] += sN[ibase + 4 * r][f] * w;
    }

    const float b  = bias[colbase + col];
    const float sc = (mat == 0) ? 0.125f : 1.0f;
    float vals[8];
    #pragma unroll
    for (int r = 0; r < 8; r++) {
        vals[r] = (acc[r] + b) * sc;
        int i = i0 + ibase + 4 * r;
        out[(size_t)h * (Nn * Dn) + (size_t)i * Dn + col] = vals[r];
    }

    if (mat == 0) {
        float (*sOut)[Dn] = (float(*)[Dn])&sW[0][0];
        __syncthreads();
        #pragma unroll
        for (int r = 0; r < 8; r++) sOut[ibase + 4 * r][col] = vals[r];
        __syncthreads();

        float wreg[Dn];
        #pragma unroll
        for (int d = 0; d < Dn; d++) wreg[d] = We[(size_t)col * INNERn + colbase + d];
        #pragma unroll
        for (int r = 0; r < 8; r++) {
            int i = i0 + ibase + 4 * r;
            float s = 0.f;
            #pragma unroll
            for (int d = 0; d < Dn; d++) s += wreg[d] * sOut[ibase + 4 * r][d];
            g_qe[(size_t)h * (Nn * DEn) + (size_t)i * DEn + col] = s;
        }
        if (col == 0) {
            #pragma unroll
            for (int r = 0; r < 8; r++) {
                int i = i0 + ibase + 4 * r;
                float sb = 0.f;
                for (int d = 0; d < Dn; d++) sb += sOut[ibase + 4 * r][d] * be[colbase + d];
                g_qbe[h * Nn + i] = sb;
            }
        }
    }
}

// ---------------- kernel 2: combined weight precompute + bvec ----------------
__global__ void __launch_bounds__(256)
wcomb_kernel(const float* __restrict__ We, const float* __restrict__ be,
             const float* __restrict__ Wo, const float* __restrict__ bo)
{
    const int b = blockIdx.x;
    const int t = threadIdx.x;
    if (b < 64) {
        const int h  = b >> 3;
        const int c0 = (b & 7) * 8 + (t >> 7) * 4;
        const int o  = t & 127;
        float acc[4] = {0.f, 0.f, 0.f, 0.f};
        for (int d = 0; d < 64; d++) {
            float wo = Wo[(size_t)(h * 64 + d) * DNn + o];
            #pragma unroll
            for (int cc = 0; cc < 4; cc++)
                acc[cc] += We[(size_t)(c0 + cc) * INNERn + h * 64 + d] * wo;
        }
        #pragma unroll
        for (int cc = 0; cc < 4; cc++)
            g_M[(size_t)(h * 64 + c0 + cc) * DNn + o] = acc[cc];
    } else {
        if (t < 128) {
            float acc = bo[t];
            for (int k = 0; k < INNERn; k++) acc += be[k] * Wo[(size_t)k * DNn + t];
            g_bvec[t] = acc;
        }
    }
}

// ---------------- kernel 3: sim = q @ k^T + qbe ----------------
__global__ void __launch_bounds__(256)
qksim_kernel(const float* __restrict__ kmat)
{
    __shared__ float sQT[64][36];
    __shared__ float sKT[64][132];

    const int i0 = blockIdx.x * 32;
    const int j0 = blockIdx.y * 128;
    const int h  = blockIdx.z;
    const int t  = threadIdx.x;

    #pragma unroll
    for (int r = 0; r < 2; r++) {
        int idx = t + 256 * r;
        int i = idx >> 4, d4 = (idx & 15) * 4;
        float4 v = *(const float4*)(g_q + (size_t)h * (Nn * Dn) + (size_t)(i0 + i) * Dn + d4);
        sQT[d4 + 0][i] = v.x; sQT[d4 + 1][i] = v.y; sQT[d4 + 2][i] = v.z; sQT[d4 + 3][i] = v.w;
    }
    #pragma unroll
    for (int r = 0; r < 8; r++) {
        int idx = t + 256 * r;
        int j = idx >> 4, d4 = (idx & 15) * 4;
        float4 v = *(const float4*)(kmat + (size_t)h * (Nn * Dn) + (size_t)(j0 + j) * Dn + d4);
        sKT[d4 + 0][j] = v.x; sKT[d4 + 1][j] = v.y; sKT[d4 + 2][j] = v.z; sKT[d4 + 3][j] = v.w;
    }
    __syncthreads();

    const int ii0 = (t >> 5) * 4;
    const int jj0 = (t & 31) * 4;
    float acc[4][4];
    #pragma unroll
    for (int u = 0; u < 4; u++)
        #pragma unroll
        for (int v = 0; v < 4; v++) acc[u][v] = 0.f;

    #pragma unroll 4
    for (int d = 0; d < 64; d++) {
        float4 rq = *(const float4*)&sQT[d][ii0];
        float4 rk = *(const float4*)&sKT[d][jj0];
        acc[0][0] += rq.x * rk.x; acc[0][1] += rq.x * rk.y; acc[0][2] += rq.x * rk.z; acc[0][3] += rq.x * rk.w;
        acc[1][0] += rq.y * rk.x; acc[1][1] += rq.y * rk.y; acc[1][2] += rq.y * rk.z; acc[1][3] += rq.y * rk.w;
        acc[2][0] += rq.z * rk.x; acc[2][1] += rq.z * rk.y; acc[2][2] += rq.z * rk.z; acc[2][3] += rq.z * rk.w;
        acc[3][0] += rq.w * rk.x; acc[3][1] += rq.w * rk.y; acc[3][2] += rq.w * rk.z; acc[3][3] += rq.w * rk.w;
    }

    #pragma unroll
    for (int u = 0; u < 4; u++) {
        float qbe = g_qbe[h * Nn + i0 + ii0 + u];
        float4 o = make_float4(acc[u][0] + qbe, acc[u][1] + qbe, acc[u][2] + qbe, acc[u][3] + qbe);
        *(float4*)(g_sim + ((size_t)(h * Nn + i0 + ii0 + u)) * Nn + j0 + jj0) = o;
    }
}

// ---------------- kernel 4: edgesim v3 — sim += qe . edges ----------------
// grid 512 (i), 256 threads. Thread owns one j-row per half.
// smem: qeP[64c][4hp] ull (2KB) + sE[256 rows][66] floats (~66KB)
#define EST 66
#define ES_SMEM (512 * 4 + 256 * EST * 4)

__global__ void __launch_bounds__(256)
edgesim2_kernel(const float* __restrict__ edges)
{
    extern __shared__ float sm[];
    ull*   sQEP = (ull*)sm;            // [c*4 + hp]
    float* sE   = sm + 512;            // [row][EST]

    const int i = blockIdx.x;
    const int t = threadIdx.x;

    // qeP[c][hp] = (qe[2hp][i][c], qe[2hp+1][i][c])
    {
        int c = t >> 2, hp = t & 3;
        float a = g_qe[(size_t)(2 * hp)     * (Nn * DEn) + (size_t)i * DEn + c];
        float b = g_qe[(size_t)(2 * hp + 1) * (Nn * DEn) + (size_t)i * DEn + c];
        sQEP[c * 4 + hp] = pk2(a, b);
    }

    for (int half = 0; half < 2; half++) {
        const int j0 = half * 256;
        // load 256 edge rows
        #pragma unroll
        for (int u = 0; u < 16; u++) {
            int idx = t + 256 * u;
            int row = idx >> 4, q4 = idx & 15;
            float4 v = *(const float4*)(edges + ((size_t)i * Nn + j0 + row) * DEn + q4 * 4);
            float* dst = sE + row * EST + q4 * 4;
            *(ull*)(dst)     = pk2(v.x, v.y);
            *(ull*)(dst + 2) = pk2(v.z, v.w);
        }
        __syncthreads();

        const int j = j0 + t;
        const float* er = sE + t * EST;
        ull acc0 = 0, acc1 = 0, acc2 = 0, acc3 = 0;
        #pragma unroll 8
        for (int c = 0; c < 64; c++) {
            float e = er[c];
            ull ed = pk2(e, e);
            const ull* qp = sQEP + c * 4;
            fma2(acc0, ed, qp[0]);
            fma2(acc1, ed, qp[1]);
            fma2(acc2, ed, qp[2]);
            fma2(acc3, ed, qp[3]);
        }
        float2 f0 = upk2(acc0), f1 = upk2(acc1), f2 = upk2(acc2), f3 = upk2(acc3);
        g_sim[((size_t)(0 * Nn + i)) * Nn + j] += f0.x;
        g_sim[((size_t)(1 * Nn + i)) * Nn + j] += f0.y;
        g_sim[((size_t)(2 * Nn + i)) * Nn + j] += f1.x;
        g_sim[((size_t)(3 * Nn + i)) * Nn + j] += f1.y;
        g_sim[((size_t)(4 * Nn + i)) * Nn + j] += f2.x;
        g_sim[((size_t)(5 * Nn + i)) * Nn + j] += f2.y;
        g_sim[((size_t)(6 * Nn + i)) * Nn + j] += f3.x;
        g_sim[((size_t)(7 * Nn + i)) * Nn + j] += f3.y;
        __syncthreads();
    }
}

// ---------------- kernel 5: row softmax (unnormalized p + 1/sum) ----------------
__global__ void __launch_bounds__(256)
softmax_kernel()
{
    const int t = threadIdx.x, w = t >> 5, l = t & 31;
    const int row = blockIdx.x * 8 + w;
    float* rp = g_sim + (size_t)row * Nn;

    float vals[16];
    float mx = -1e30f;
    #pragma unroll
    for (int jc = 0; jc < 16; jc++) {
        vals[jc] = rp[jc * 32 + l];
        mx = fmaxf(mx, vals[jc]);
    }
    #pragma unroll
    for (int off = 16; off > 0; off >>= 1) mx = fmaxf(mx, __shfl_xor_sync(0xffffffffu, mx, off));
    float s = 0.f;
    #pragma unroll
    for (int jc = 0; jc < 16; jc++) {
        float e = __expf(vals[jc] - mx);
        s += e;
        rp[jc * 32 + l] = e;
    }
    #pragma unroll
    for (int off = 16; off > 0; off >>= 1) s += __shfl_xor_sync(0xffffffffu, s, off);
    if (l == 0) g_sinv[row] = 1.0f / s;
}

// ---------------- kernel 6: att = (p @ v) * sinv ----------------
__global__ void __launch_bounds__(256)
pv_kernel(const float* __restrict__ vmat)
{
    __shared__ float sPT[64][36];
    __shared__ float sV [64][68];

    const int i0 = blockIdx.x * 32;
    const int h  = blockIdx.y;
    const int t  = threadIdx.x;
    const int i0t = (t >> 4) * 2;
    const int d0  = (t & 15) * 4;

    float acc[2][4];
    #pragma unroll
    for (int u = 0; u < 2; u++)
        #pragma unroll
        for (int v = 0; v < 4; v++) acc[u][v] = 0.f;

    for (int jc = 0; jc < 8; jc++) {
        const int j0 = jc * 64;
        #pragma unroll
        for (int r = 0; r < 2; r++) {
            int idx = t + 256 * r;
            int ii = idx >> 4, jj4 = (idx & 15) * 4;
            float4 v = *(const float4*)(g_sim + ((size_t)(h * Nn + i0 + ii)) * Nn + j0 + jj4);
            sPT[jj4 + 0][ii] = v.x; sPT[jj4 + 1][ii] = v.y; sPT[jj4 + 2][ii] = v.z; sPT[jj4 + 3][ii] = v.w;
        }
        #pragma unroll
        for (int r = 0; r < 4; r++) {
            int idx = t + 256 * r;
            int jj = idx >> 4, d4 = (idx & 15) * 4;
            *(float4*)&sV[jj][d4] = *(const float4*)(vmat + (size_t)h * (Nn * Dn) + (size_t)(j0 + jj) * Dn + d4);
        }
        __syncthreads();

        #pragma unroll 4
        for (int jj = 0; jj < 64; jj++) {
            float2 rp = *(const float2*)&sPT[jj][i0t];
            float4 rv = *(const float4*)&sV[jj][d0];
            acc[0][0] += rp.x * rv.x; acc[0][1] += rp.x * rv.y; acc[0][2] += rp.x * rv.z; acc[0][3] += rp.x * rv.w;
            acc[1][0] += rp.y * rv.x; acc[1][1] += rp.y * rv.y; acc[1][2] += rp.y * rv.z; acc[1][3] += rp.y * rv.w;
        }
        __syncthreads();
    }

    #pragma unroll
    for (int u = 0; u < 2; u++) {
        float s = g_sinv[h * Nn + i0 + i0t + u];
        float4 o = make_float4(acc[u][0] * s, acc[u][1] * s, acc[u][2] * s, acc[u][3] * s);
        *(float4*)(g_att + (size_t)h * (Nn * Dn) + (size_t)(i0 + i0t + u) * Dn + d0) = o;
    }
}

// ---------------- kernel 7: ew v2 = (p @ edges) * sinv ----------------
// grid 512 (i), 256 threads. Thread owns (c, j-quarter); accumulate over j.
// smem: sPT[512 j][5 slot] ull (20.5KB) + sSinv + sRed[4][64][4] ull (8KB) + sE[128][66] (33.8KB)
#define EW_PT   0
#define EW_SINV (512 * 5 * 2)                 // float index
#define EW_RED  (EW_SINV + 16)
#define EW_E    (EW_RED + 4 * 64 * 4 * 2)
#define EW_SMEM ((EW_E + 128 * EST) * 4)

__global__ void __launch_bounds__(256)
ew2_kernel(const float* __restrict__ edges)
{
    extern __shared__ float sm[];
    ull*   sPT   = (ull*)sm;                 // [j*5 + hp]
    float* sSinv = sm + EW_SINV;
    ull*   sRed  = (ull*)(sm + EW_RED);      // [jq*256 + c*4 + hp]
    float* sE    = sm + EW_E;                // [row][EST]

    const int i = blockIdx.x;
    const int t = threadIdx.x;

    // load + transpose p into head-pair packed form
    #pragma unroll
    for (int hp = 0; hp < 4; hp++) {
        #pragma unroll
        for (int jj = 0; jj < 2; jj++) {
            int j = jj * 256 + t;
            float a = g_sim[((size_t)((2 * hp)     * Nn + i)) * Nn + j];
            float b = g_sim[((size_t)((2 * hp + 1) * Nn + i)) * Nn + j];
            sPT[j * 5 + hp] = pk2(a, b);
        }
    }
    if (t < 8) sSinv[t] = g_sinv[t * Nn + i];

    const int c  = t & 63;
    const int jq = t >> 6;
    ull acc0 = 0, acc1 = 0, acc2 = 0, acc3 = 0;

    for (int tile = 0; tile < 4; tile++) {
        const int jt = tile * 128;
        #pragma unroll
        for (int u = 0; u < 8; u++) {
            int idx = t + 256 * u;
            int row = idx >> 4, q4 = idx & 15;
            float4 v = *(const float4*)(edges + ((size_t)i * Nn + jt + row) * DEn + q4 * 4);
            float* dst = sE + row * EST + q4 * 4;
            *(ull*)(dst)     = pk2(v.x, v.y);
            *(ull*)(dst + 2) = pk2(v.z, v.w);
        }
        __syncthreads();

        const int jbase = jq * 32;
        #pragma unroll 4
        for (int jj = 0; jj < 32; jj++) {
            int jl = jbase + jj;
            float e = sE[jl * EST + c];
            ull ed = pk2(e, e);
            const ull* pp = sPT + (jt + jl) * 5;
            fma2(acc0, pp[0], ed);
            fma2(acc1, pp[1], ed);
            fma2(acc2, pp[2], ed);
            fma2(acc3, pp[3], ed);
        }
        __syncthreads();
    }

    sRed[jq * 256 + c * 4 + 0] = acc0;
    sRed[jq * 256 + c * 4 + 1] = acc1;
    sRed[jq * 256 + c * 4 + 2] = acc2;
    sRed[jq * 256 + c * 4 + 3] = acc3;
    __syncthreads();

    {
        const int cc = t >> 2, hp = t & 3;
        float ax = 0.f, ay = 0.f;
        #pragma unroll
        for (int q = 0; q < 4; q++) {
            float2 f = upk2(sRed[q * 256 + cc * 4 + hp]);
            ax += f.x; ay += f.y;
        }
        g_ew[(size_t)(2 * hp)     * (Nn * DEn) + (size_t)i * DEn + cc] = ax * sSinv[2 * hp];
        g_ew[(size_t)(2 * hp + 1) * (Nn * DEn) + (size_t)i * DEn + cc] = ay * sSinv[2 * hp + 1];
    }
}

// ---------------- kernel 8: out = [att|ew] @ [Wo;M] + bvec (tiled GEMM) --------
// grid (32 i-tiles, 4 col-tiles), block 256. Output tile 16 x 32.
__global__ void __launch_bounds__(256)
fuse_out_kernel(const float* __restrict__ Wo, float* __restrict__ out)
{
    __shared__ float sA[16][132];
    __shared__ float sW[128][36];

    const int t = threadIdx.x;
    const int i0 = blockIdx.x * 16;
    const int c0 = blockIdx.y * 32;

    const int r  = t >> 4;
    const int cc = (t & 15) * 2;
    ull acc = 0;

    for (int kc = 0; kc < 8; kc++) {
        const int kb = kc * 128;
        // A tile: 16 rows x 128 k
        #pragma unroll
        for (int u = 0; u < 2; u++) {
            int idx = t + 256 * u;
            int row = idx >> 5, kk4 = (idx & 31) * 4;
            int k = kb + kk4;
            float4 v;
            if (k < 512) {
                int h = k >> 6, d = k & 63;
                v = *(const float4*)(g_att + (size_t)h * (Nn * Dn) + (size_t)(i0 + row) * Dn + d);
            } else {
                int k2 = k - 512;
                int h = k2 >> 6, d = k2 & 63;
                v = *(const float4*)(g_ew + (size_t)h * (Nn * DEn) + (size_t)(i0 + row) * DEn + d);
            }
            *(float4*)&sA[row][kk4] = v;
        }
        // W tile: 128 k x 32 cols
        #pragma unroll
        for (int u = 0; u < 4; u++) {
            int idx = t + 256 * u;
            int kr = idx >> 3, q = idx & 7;
            int k = kb + kr;
            float4 v;
            if (k < 512) v = *(const float4*)(Wo  + (size_t)k * DNn + c0 + q * 4);
            else         v = *(const float4*)(g_M + (size_t)(k - 512) * DNn + c0 + q * 4);
            *(float4*)&sW[kr][q * 4] = v;
        }
        __syncthreads();

        #pragma unroll 8
        for (int kk = 0; kk < 128; kk++) {
            float a = sA[r][kk];
            ull ad = pk2(a, a);
            ull wv = *(const ull*)&sW[kk][cc];
            fma2(acc, ad, wv);
        }
        __syncthreads();
    }

    float2 f = upk2(acc);
    f.x += g_bvec[c0 + cc];
    f.y += g_bvec[c0 + cc + 1];
    *(float2*)(out + (size_t)(i0 + r) * DNn + c0 + cc) = f;
}

// ---------------- launch ----------------
extern "C" void kernel_launch(void* const* d_in, const int* in_sizes, int n_in,
                              void* d_out, int out_size)
{
    const float* nodes = (const float*)d_in[0];
    const float* edges = (const float*)d_in[1];
    const float* Wq = (const float*)d_in[3];
    const float* bq = (const float*)d_in[4];
    const float* Wk = (const float*)d_in[5];
    const float* bk = (const float*)d_in[6];
    const float* Wv = (const float*)d_in[7];
    const float* bv = (const float*)d_in[8];
    const float* We = (const float*)d_in[9];
    const float* be = (const float*)d_in[10];
    const float* Wo = (const float*)d_in[11];
    const float* bo = (const float*)d_in[12];
    float* out = (float*)d_out;

    float* kptr; float* vptr;
    cudaGetSymbolAddress((void**)&kptr, g_k);
    cudaGetSymbolAddress((void**)&vptr, g_v);

    cudaFuncSetAttribute(edgesim2_kernel, cudaFuncAttributeMaxDynamicSharedMemorySize, ES_SMEM);
    cudaFuncSetAttribute(ew2_kernel, cudaFuncAttributeMaxDynamicSharedMemorySize, EW_SMEM);

    dim3 g1(16, 24);
    qkv_kernel<<<g1, 256>>>(nodes, Wq, bq, Wk, bk, Wv, bv, We, be);
    wcomb_kernel<<<65, 256>>>(We, be, Wo, bo);
    qksim_kernel<<<dim3(16, 4, 8), 256>>>(kptr);
    edgesim2_kernel<<<Nn, 256, ES_SMEM>>>(edges);
    softmax_kernel<<<Nn * Hn / 8, 256>>>();
    pv_kernel<<<dim3(16, 8), 256>>>(vptr);
    ew2_kernel<<<Nn, 256, EW_SMEM>>>(edges);
    fuse_out_kernel<<<dim3(32, 4), 256>>>(Wo, out);
}

// round 6
// speedup vs baseline: 1.3637x; 1.0887x over previous
#include <cuda_runtime.h>
#include <math.h>

#define Hn     8
#define Nn     512
#define Dn     64
#define DNn    128
#define DEn    64
#define INNERn 512

typedef unsigned long long ull;

__device__ __forceinline__ ull pk2(float lo, float hi) {
    ull r; asm("mov.b64 %0,{%1,%2};" : "=l"(r) : "f"(lo), "f"(hi)); return r;
}
__device__ __forceinline__ float2 upk2(ull v) {
    float2 r; asm("mov.b64 {%0,%1},%2;" : "=f"(r.x), "=f"(r.y) : "l"(v)); return r;
}
__device__ __forceinline__ void fma2(ull& d, ull a, ull b) {
    asm("fma.rn.f32x2 %0,%1,%2,%3;" : "=l"(d) : "l"(a), "l"(b), "l"(d));
}
__device__ __forceinline__ void add2(ull& d, ull a) {
    asm("add.rn.f32x2 %0,%1,%2;" : "=l"(d) : "l"(d), "l"(a));
}

// ---------------- scratch ----------------
__device__ float g_q  [Hn * Nn * Dn];
__device__ float g_k  [Hn * Nn * Dn];
__device__ float g_v  [Hn * Nn * Dn];
__device__ float g_qe [Hn * Nn * DEn];
__device__ float g_qbe[Hn * Nn];
__device__ float g_sim[Hn * Nn * Nn];    // qk logits, then unnormalized p
__device__ float g_sinv[Hn * Nn];
__device__ float g_att[Hn * Nn * Dn];
__device__ float g_ew [Hn * Nn * DEn];
__device__ float g_M  [INNERn * DNn];
__device__ float g_bvec[DNn];

// ---------------- kernel 1: QKV projection (+ fused qe, qbe) --------
__global__ void __launch_bounds__(256)
qkv_kernel(const float* __restrict__ nodes,
           const float* __restrict__ Wq, const float* __restrict__ bq,
           const float* __restrict__ Wk, const float* __restrict__ bk,
           const float* __restrict__ Wv, const float* __restrict__ bv,
           const float* __restrict__ We, const float* __restrict__ be)
{
    __shared__ float sN[32][DNn];
    __shared__ float sW[DNn][64];

    const int it = blockIdx.x;
    const int ct = blockIdx.y;
    const int mat = ct >> 3;
    const int h   = ct & 7;
    const int colbase = h * 64;
    const float* W    = (mat == 0) ? Wq : (mat == 1 ? Wk : Wv);
    const float* bias = (mat == 0) ? bq : (mat == 1 ? bk : bv);
    float* out        = (mat == 0) ? g_q : (mat == 1 ? g_k : g_v);

    const int i0 = it * 32;
    const int t  = threadIdx.x;

    {
        const float4* nf = (const float4*)(nodes + (size_t)i0 * DNn);
        float4* sNf = (float4*)&sN[0][0];
        #pragma unroll
        for (int r = 0; r < 4; r++) sNf[t + 256 * r] = nf[t + 256 * r];
    }
    #pragma unroll
    for (int r = 0; r < 8; r++) {
        int idx = t + 256 * r;
        int f = idx >> 4, c4 = idx & 15;
        ((float4*)&sW[f][0])[c4] = *(const float4*)(W + (size_t)f * INNERn + colbase + c4 * 4);
    }
    __syncthreads();

    const int col   = t & 63;
    const int ibase = t >> 6;
    float acc[8];
    #pragma unroll
    for (int r = 0; r < 8; r++) acc[r] = 0.f;

    for (int f = 0; f < DNn; f++) {
        float w = sW[f][col];
        #pragma unroll
        for (int r = 0; r < 8; r++) acc[r] += sN[ibase + 4 * r][f] * w;
    }

    const float b  = bias[colbase + col];
    const float sc = (mat == 0) ? 0.125f : 1.0f;
    float vals[8];
    #pragma unroll
    for (int r = 0; r < 8; r++) {
        vals[r] = (acc[r] + b) * sc;
        int i = i0 + ibase + 4 * r;
        out[(size_t)h * (Nn * Dn) + (size_t)i * Dn + col] = vals[r];
    }

    if (mat == 0) {
        float (*sOut)[Dn] = (float(*)[Dn])&sW[0][0];
        __syncthreads();
        #pragma unroll
        for (int r = 0; r < 8; r++) sOut[ibase + 4 * r][col] = vals[r];
        __syncthreads();

        float wreg[Dn];
        #pragma unroll
        for (int d = 0; d < Dn; d++) wreg[d] = We[(size_t)col * INNERn + colbase + d];
        #pragma unroll
        for (int r = 0; r < 8; r++) {
            int i = i0 + ibase + 4 * r;
            float s = 0.f;
            #pragma unroll
            for (int d = 0; d < Dn; d++) s += wreg[d] * sOut[ibase + 4 * r][d];
            g_qe[(size_t)h * (Nn * DEn) + (size_t)i * DEn + col] = s;
        }
        if (col == 0) {
            #pragma unroll
            for (int r = 0; r < 8; r++) {
                int i = i0 + ibase + 4 * r;
                float sb = 0.f;
                for (int d = 0; d < Dn; d++) sb += sOut[ibase + 4 * r][d] * be[colbase + d];
                g_qbe[h * Nn + i] = sb;
            }
        }
    }
}

// ---------------- kernel 2: combined weight precompute + bvec ----------------
__global__ void __launch_bounds__(256)
wcomb_kernel(const float* __restrict__ We, const float* __restrict__ be,
             const float* __restrict__ Wo, const float* __restrict__ bo)
{
    const int b = blockIdx.x;
    const int t = threadIdx.x;
    if (b < 64) {
        const int h  = b >> 3;
        const int c0 = (b & 7) * 8 + (t >> 7) * 4;
        const int o  = t & 127;
        float acc[4] = {0.f, 0.f, 0.f, 0.f};
        for (int d = 0; d < 64; d++) {
            float wo = Wo[(size_t)(h * 64 + d) * DNn + o];
            #pragma unroll
            for (int cc = 0; cc < 4; cc++)
                acc[cc] += We[(size_t)(c0 + cc) * INNERn + h * 64 + d] * wo;
        }
        #pragma unroll
        for (int cc = 0; cc < 4; cc++)
            g_M[(size_t)(h * 64 + c0 + cc) * DNn + o] = acc[cc];
    } else {
        if (t < 128) {
            float acc = bo[t];
            for (int k = 0; k < INNERn; k++) acc += be[k] * Wo[(size_t)k * DNn + t];
            g_bvec[t] = acc;
        }
    }
}

// ---------------- kernel 3: sim = q @ k^T + qbe ----------------
__global__ void __launch_bounds__(256)
qksim_kernel(const float* __restrict__ kmat)
{
    __shared__ float sQT[64][36];
    __shared__ float sKT[64][132];

    const int i0 = blockIdx.x * 32;
    const int j0 = blockIdx.y * 128;
    const int h  = blockIdx.z;
    const int t  = threadIdx.x;

    #pragma unroll
    for (int r = 0; r < 2; r++) {
        int idx = t + 256 * r;
        int i = idx >> 4, d4 = (idx & 15) * 4;
        float4 v = *(const float4*)(g_q + (size_t)h * (Nn * Dn) + (size_t)(i0 + i) * Dn + d4);
        sQT[d4 + 0][i] = v.x; sQT[d4 + 1][i] = v.y; sQT[d4 + 2][i] = v.z; sQT[d4 + 3][i] = v.w;
    }
    #pragma unroll
    for (int r = 0; r < 8; r++) {
        int idx = t + 256 * r;
        int j = idx >> 4, d4 = (idx & 15) * 4;
        float4 v = *(const float4*)(kmat + (size_t)h * (Nn * Dn) + (size_t)(j0 + j) * Dn + d4);
        sKT[d4 + 0][j] = v.x; sKT[d4 + 1][j] = v.y; sKT[d4 + 2][j] = v.z; sKT[d4 + 3][j] = v.w;
    }
    __syncthreads();

    const int ii0 = (t >> 5) * 4;
    const int jj0 = (t & 31) * 4;
    float acc[4][4];
    #pragma unroll
    for (int u = 0; u < 4; u++)
        #pragma unroll
        for (int v = 0; v < 4; v++) acc[u][v] = 0.f;

    #pragma unroll 4
    for (int d = 0; d < 64; d++) {
        float4 rq = *(const float4*)&sQT[d][ii0];
        float4 rk = *(const float4*)&sKT[d][jj0];
        acc[0][0] += rq.x * rk.x; acc[0][1] += rq.x * rk.y; acc[0][2] += rq.x * rk.z; acc[0][3] += rq.x * rk.w;
        acc[1][0] += rq.y * rk.x; acc[1][1] += rq.y * rk.y; acc[1][2] += rq.y * rk.z; acc[1][3] += rq.y * rk.w;
        acc[2][0] += rq.z * rk.x; acc[2][1] += rq.z * rk.y; acc[2][2] += rq.z * rk.z; acc[2][3] += rq.z * rk.w;
        acc[3][0] += rq.w * rk.x; acc[3][1] += rq.w * rk.y; acc[3][2] += rq.w * rk.z; acc[3][3] += rq.w * rk.w;
    }

    #pragma unroll
    for (int u = 0; u < 4; u++) {
        float qbe = g_qbe[h * Nn + i0 + ii0 + u];
        float4 o = make_float4(acc[u][0] + qbe, acc[u][1] + qbe, acc[u][2] + qbe, acc[u][3] + qbe);
        *(float4*)(g_sim + ((size_t)(h * Nn + i0 + ii0 + u)) * Nn + j0 + jj0) = o;
    }
}

// ---------------- kernel 4: edge_mega — edgesim + softmax + ew fused --------
// grid 512 (node i), 256 threads, 69.7KB smem -> 3 CTAs/SM
#define EMS_SIM  0                    // 4096 floats: [h][j]
#define EMS_QEP  4096                 // 512 floats = 256 ull: [c][hp]
#define EMS_SINV 4608                 // 16 floats
#define EMS_RED  4624                 // 4096 floats = 2048 ull
#define EMS_E    8720                 // 128 rows x 68
#define EM_SMEM  ((EMS_E + 128 * 68) * 4)

__global__ void __launch_bounds__(256, 3)
edge_mega_kernel(const float* __restrict__ edges)
{
    extern __shared__ float sm[];
    float* sSim  = sm + EMS_SIM;
    ull*   sQEP  = (ull*)(sm + EMS_QEP);
    float* sSinv = sm + EMS_SINV;
    ull*   sRed  = (ull*)(sm + EMS_RED);
    float* sE    = sm + EMS_E;

    const int i = blockIdx.x;
    const int t = threadIdx.x;
    const int w = t >> 5, l = t & 31;

    // load qk logits into smem
    #pragma unroll
    for (int r = 0; r < 4; r++) {
        int idx = t + 256 * r;
        int h = idx >> 7, j4 = (idx & 127) * 4;
        *(float4*)&sSim[h * 512 + j4] = *(const float4*)(g_sim + ((size_t)(h * Nn + i)) * Nn + j4);
    }
    // qe head-pairs: sQEP[c*4+hp] = (qe[2hp], qe[2hp+1])
    {
        int c = t >> 2, hp = t & 3;
        float a = g_qe[(size_t)(2 * hp)     * (Nn * DEn) + (size_t)i * DEn + c];
        float b = g_qe[(size_t)(2 * hp + 1) * (Nn * DEn) + (size_t)i * DEn + c];
        sQEP[c * 4 + hp] = pk2(a, b);
    }

    // ======== phase 1: sim += qe . edges, 128-row tiles ========
    const int jl = t & 63, qq = t >> 6;     // thread: rows {jl, jl+64}, c-range qq*16..+15
    for (int tile = 0; tile < 4; tile++) {
        const int j0 = tile * 128;
        #pragma unroll
        for (int u = 0; u < 8; u++) {
            int idx = t + 256 * u;
            int row = idx >> 4, q4 = (idx & 15) * 4;
            *(float4*)&sE[row * 68 + q4] = *(const float4*)(edges + ((size_t)i * Nn + j0 + row) * DEn + q4);
        }
        __syncthreads();

        ull a0[4] = {0, 0, 0, 0}, a1[4] = {0, 0, 0, 0};
        const int c0 = qq * 16;
        #pragma unroll
        for (int cc = 0; cc < 4; cc++) {
            const int cb = c0 + cc * 4;
            ull qr[4][4];
            #pragma unroll
            for (int k = 0; k < 4; k++)
                #pragma unroll
                for (int hp = 0; hp < 4; hp++)
                    qr[k][hp] = sQEP[(cb + k) * 4 + hp];    // warp-uniform
            float4 e0 = *(const float4*)&sE[jl * 68 + cb];
            float4 e1 = *(const float4*)&sE[(jl + 64) * 68 + cb];
            ull ed0[4] = {pk2(e0.x, e0.x), pk2(e0.y, e0.y), pk2(e0.z, e0.z), pk2(e0.w, e0.w)};
            ull ed1[4] = {pk2(e1.x, e1.x), pk2(e1.y, e1.y), pk2(e1.z, e1.z), pk2(e1.w, e1.w)};
            #pragma unroll
            for (int k = 0; k < 4; k++)
                #pragma unroll
                for (int hp = 0; hp < 4; hp++) {
                    fma2(a0[hp], ed0[k], qr[k][hp]);
                    fma2(a1[hp], ed1[k], qr[k][hp]);
                }
        }
        // partials: sRed[(hp*4+qq)*128 + row]
        #pragma unroll
        for (int hp = 0; hp < 4; hp++) {
            sRed[(hp * 4 + qq) * 128 + jl]      = a0[hp];
            sRed[(hp * 4 + qq) * 128 + jl + 64] = a1[hp];
        }
        __syncthreads();

        // reduce over qq, add into sSim
        #pragma unroll
        for (int u = 0; u < 2; u++) {
            int it = t + 256 * u;
            int hp = it >> 7, row = it & 127;
            float ax = 0.f, ay = 0.f;
            #pragma unroll
            for (int q = 0; q < 4; q++) {
                float2 f = upk2(sRed[(hp * 4 + q) * 128 + row]);
                ax += f.x; ay += f.y;
            }
            sSim[(2 * hp) * 512 + j0 + row]     += ax;
            sSim[(2 * hp + 1) * 512 + j0 + row] += ay;
        }
        __syncthreads();
    }

    // ======== phase 2: softmax (warp = head) ========
    {
        float vals[16];
        float mx = -1e30f;
        #pragma unroll
        for (int jc = 0; jc < 16; jc++) {
            vals[jc] = sSim[w * 512 + jc * 32 + l];
            mx = fmaxf(mx, vals[jc]);
        }
        #pragma unroll
        for (int off = 16; off > 0; off >>= 1) mx = fmaxf(mx, __shfl_xor_sync(0xffffffffu, mx, off));
        float s = 0.f;
        #pragma unroll
        for (int jc = 0; jc < 16; jc++) {
            float e = __expf(vals[jc] - mx);
            s += e;
            sSim[w * 512 + jc * 32 + l] = e;
        }
        #pragma unroll
        for (int off = 16; off > 0; off >>= 1) s += __shfl_xor_sync(0xffffffffu, s, off);
        if (l == 0) sSinv[w] = 1.0f / s;
    }
    __syncthreads();

    // write unnormalized p + sinv for pv kernel
    #pragma unroll
    for (int r = 0; r < 4; r++) {
        int idx = t + 256 * r;
        int h = idx >> 7, j4 = (idx & 127) * 4;
        *(float4*)(g_sim + ((size_t)(h * Nn + i)) * Nn + j4) = *(const float4*)&sSim[h * 512 + j4];
    }
    if (t < 8) g_sinv[t * Nn + i] = sSinv[t];

    // ======== phase 3: ew = (p @ edges) * sinv ========
    const int cq = t & 15, jg = t >> 4;     // thread: 4 c's, 8 rows per tile
    const int c0p = cq * 4;
    ull b[4][4];
    #pragma unroll
    for (int k = 0; k < 4; k++)
        #pragma unroll
        for (int hp = 0; hp < 4; hp++) b[k][hp] = 0ull;

    for (int tile = 0; tile < 4; tile++) {
        const int j0 = tile * 128;
        #pragma unroll
        for (int u = 0; u < 8; u++) {
            int idx = t + 256 * u;
            int row = idx >> 4, q4 = (idx & 15) * 4;
            *(float4*)&sE[row * 68 + q4] = *(const float4*)(edges + ((size_t)i * Nn + j0 + row) * DEn + q4);
        }
        __syncthreads();

        #pragma unroll
        for (int jj = 0; jj < 8; jj++) {
            const int j = jg * 8 + jj;
            const int jglob = j0 + j;
            ull pp[4];
            #pragma unroll
            for (int hp = 0; hp < 4; hp++)
                pp[hp] = pk2(sSim[(2 * hp) * 512 + jglob], sSim[(2 * hp + 1) * 512 + jglob]);
            float4 e4 = *(const float4*)&sE[j * 68 + c0p];
            ull ed[4] = {pk2(e4.x, e4.x), pk2(e4.y, e4.y), pk2(e4.z, e4.z), pk2(e4.w, e4.w)};
            #pragma unroll
            for (int k = 0; k < 4; k++)
                #pragma unroll
                for (int hp = 0; hp < 4; hp++)
                    fma2(b[k][hp], pp[hp], ed[k]);
        }
        __syncthreads();
    }

    // intra-warp jg-pair reduce (lanes l and l+16 hold jg = 2w, 2w+1)
    #pragma unroll
    for (int k = 0; k < 4; k++)
        #pragma unroll
        for (int hp = 0; hp < 4; hp++) {
            ull o = __shfl_down_sync(0xffffffffu, b[k][hp], 16);
            add2(b[k][hp], o);
        }
    if (l < 16) {
        const int jg2 = w;
        #pragma unroll
        for (int k = 0; k < 4; k++)
            #pragma unroll
            for (int hp = 0; hp < 4; hp++)
                sRed[(k * 4 + hp) * 128 + jg2 * 16 + cq] = b[k][hp];
    }
    __syncthreads();

    // final reduce + store ew
    {
        const int hp = t >> 6, c = t & 63;
        const int k = c & 3, cq2 = c >> 2;
        float ax = 0.f, ay = 0.f;
        #pragma unroll
        for (int jg2 = 0; jg2 < 8; jg2++) {
            float2 f = upk2(sRed[(k * 4 + hp) * 128 + jg2 * 16 + cq2]);
            ax += f.x; ay += f.y;
        }
        g_ew[(size_t)(2 * hp)     * (Nn * DEn) + (size_t)i * DEn + c] = ax * sSinv[2 * hp];
        g_ew[(size_t)(2 * hp + 1) * (Nn * DEn) + (size_t)i * DEn + c] = ay * sSinv[2 * hp + 1];
    }
}

// ---------------- kernel 5: att = (p @ v) * sinv ----------------
__global__ void __launch_bounds__(256)
pv_kernel(const float* __restrict__ vmat)
{
    __shared__ float sPT[64][36];
    __shared__ float sV [64][68];

    const int i0 = blockIdx.x * 32;
    const int h  = blockIdx.y;
    const int t  = threadIdx.x;
    const int i0t = (t >> 4) * 2;
    const int d0  = (t & 15) * 4;

    float acc[2][4];
    #pragma unroll
    for (int u = 0; u < 2; u++)
        #pragma unroll
        for (int v = 0; v < 4; v++) acc[u][v] = 0.f;

    for (int jc = 0; jc < 8; jc++) {
        const int j0 = jc * 64;
        #pragma unroll
        for (int r = 0; r < 2; r++) {
            int idx = t + 256 * r;
            int ii = idx >> 4, jj4 = (idx & 15) * 4;
            float4 v = *(const float4*)(g_sim + ((size_t)(h * Nn + i0 + ii)) * Nn + j0 + jj4);
            sPT[jj4 + 0][ii] = v.x; sPT[jj4 + 1][ii] = v.y; sPT[jj4 + 2][ii] = v.z; sPT[jj4 + 3][ii] = v.w;
        }
        #pragma unroll
        for (int r = 0; r < 4; r++) {
            int idx = t + 256 * r;
            int jj = idx >> 4, d4 = (idx & 15) * 4;
            *(float4*)&sV[jj][d4] = *(const float4*)(vmat + (size_t)h * (Nn * Dn) + (size_t)(j0 + jj) * Dn + d4);
        }
        __syncthreads();

        #pragma unroll 4
        for (int jj = 0; jj < 64; jj++) {
            float2 rp = *(const float2*)&sPT[jj][i0t];
            float4 rv = *(const float4*)&sV[jj][d0];
            acc[0][0] += rp.x * rv.x; acc[0][1] += rp.x * rv.y; acc[0][2] += rp.x * rv.z; acc[0][3] += rp.x * rv.w;
            acc[1][0] += rp.y * rv.x; acc[1][1] += rp.y * rv.y; acc[1][2] += rp.y * rv.z; acc[1][3] += rp.y * rv.w;
        }
        __syncthreads();
    }

    #pragma unroll
    for (int u = 0; u < 2; u++) {
        float s = g_sinv[h * Nn + i0 + i0t + u];
        float4 o = make_float4(acc[u][0] * s, acc[u][1] * s, acc[u][2] * s, acc[u][3] * s);
        *(float4*)(g_att + (size_t)h * (Nn * Dn) + (size_t)(i0 + i0t + u) * Dn + d0) = o;
    }
}

// ---------------- kernel 6: out = [att|ew] @ [Wo;M] + bvec (tiled GEMM) --------
__global__ void __launch_bounds__(256)
fuse_out_kernel(const float* __restrict__ Wo, float* __restrict__ out)
{
    __shared__ float sA[16][132];
    __shared__ float sW[128][36];

    const int t = threadIdx.x;
    const int i0 = blockIdx.x * 16;
    const int c0 = blockIdx.y * 32;

    const int r  = t >> 4;
    const int cc = (t & 15) * 2;
    ull acc = 0;

    for (int kc = 0; kc < 8; kc++) {
        const int kb = kc * 128;
        #pragma unroll
        for (int u = 0; u < 2; u++) {
            int idx = t + 256 * u;
            int row = idx >> 5, kk4 = (idx & 31) * 4;
            int k = kb + kk4;
            float4 v;
            if (k < 512) {
                int h = k >> 6, d = k & 63;
                v = *(const float4*)(g_att + (size_t)h * (Nn * Dn) + (size_t)(i0 + row) * Dn + d);
            } else {
                int k2 = k - 512;
                int h = k2 >> 6, d = k2 & 63;
                v = *(const float4*)(g_ew + (size_t)h * (Nn * DEn) + (size_t)(i0 + row) * DEn + d);
            }
            *(float4*)&sA[row][kk4] = v;
        }
        #pragma unroll
        for (int u = 0; u < 4; u++) {
            int idx = t + 256 * u;
            int kr = idx >> 3, q = idx & 7;
            int k = kb + kr;
            float4 v;
            if (k < 512) v = *(const float4*)(Wo  + (size_t)k * DNn + c0 + q * 4);
            else         v = *(const float4*)(g_M + (size_t)(k - 512) * DNn + c0 + q * 4);
            *(float4*)&sW[kr][q * 4] = v;
        }
        __syncthreads();

        #pragma unroll 8
        for (int kk = 0; kk < 128; kk++) {
            float a = sA[r][kk];
            ull ad = pk2(a, a);
            ull wv = *(const ull*)&sW[kk][cc];
            fma2(acc, ad, wv);
        }
        __syncthreads();
    }

    float2 f = upk2(acc);
    f.x += g_bvec[c0 + cc];
    f.y += g_bvec[c0 + cc + 1];
    *(float2*)(out + (size_t)(i0 + r) * DNn + c0 + cc) = f;
}

// ---------------- launch ----------------
extern "C" void kernel_launch(void* const* d_in, const int* in_sizes, int n_in,
                              void* d_out, int out_size)
{
    const float* nodes = (const float*)d_in[0];
    const float* edges = (const float*)d_in[1];
    const float* Wq = (const float*)d_in[3];
    const float* bq = (const float*)d_in[4];
    const float* Wk = (const float*)d_in[5];
    const float* bk = (const float*)d_in[6];
    const float* Wv = (const float*)d_in[7];
    const float* bv = (const float*)d_in[8];
    const float* We = (const float*)d_in[9];
    const float* be = (const float*)d_in[10];
    const float* Wo = (const float*)d_in[11];
    const float* bo = (const float*)d_in[12];
    float* out = (float*)d_out;

    float* kptr; float* vptr;
    cudaGetSymbolAddress((void**)&kptr, g_k);
    cudaGetSymbolAddress((void**)&vptr, g_v);

    cudaFuncSetAttribute(edge_mega_kernel, cudaFuncAttributeMaxDynamicSharedMemorySize, EM_SMEM);

    dim3 g1(16, 24);
    qkv_kernel<<<g1, 256>>>(nodes, Wq, bq, Wk, bk, Wv, bv, We, be);
    wcomb_kernel<<<65, 256>>>(We, be, Wo, bo);
    qksim_kernel<<<dim3(16, 4, 8), 256>>>(kptr);
    edge_mega_kernel<<<Nn, 256, EM_SMEM>>>(edges);
    pv_kernel<<<dim3(16, 8), 256>>>(vptr);
    fuse_out_kernel<<<dim3(32, 4), 256>>>(Wo, out);
}